// round 1
// baseline (speedup 1.0000x reference)
#include <cuda_runtime.h>
#include <math.h>

// Problem dims
#define B_   128
#define T_   1024
#define IN_  256
#define H_   512
#define OUT_ 256

// ---------------- device scratch (no allocations allowed) ----------------
__device__ float g_U[(size_t)B_ * T_ * H_];   // 256 MB: precomputed x@w_ih0^T + b_ih0 + b_hh0, layout [b*T+t][H]
__device__ float g_h0[2][B_ * H_];            // layer0 hidden, ping-pong by t&1
__device__ float g_h1[2][B_ * H_];            // layer1 hidden, ping-pong by t&1
__device__ unsigned g_bar;                    // grid barrier counter (monotonic per launch)

// ---------------- init: reset barrier, load initial hidden state ----------------
__global__ void init_kernel(const float* __restrict__ h0in) {
    int idx = blockIdx.x * blockDim.x + threadIdx.x;
    if (idx == 0) g_bar = 0u;
    if (idx < B_ * H_) {
        g_h0[1][idx] = h0in[idx];            // layer 0 initial state (read at t=0, parity 1-p = 1)
        g_h1[1][idx] = h0in[B_ * H_ + idx];  // layer 1 initial state
    }
}

// ---------------- precompute GEMM: U = X @ w_ih0^T + (b_ih0 + b_hh0) ----------------
// M = B*T = 131072, N = H = 512, K = IN = 256.  CTA tile 128x64, K-chunks of 32.
#define PG_M   128
#define PG_N   64
#define PG_K   32
#define PG_PAD 36   // row stride (floats); 36*4=144 bytes, 16B-aligned for float4 STS

__global__ __launch_bounds__(256) void pre_gemm(
    const float* __restrict__ X, const float* __restrict__ W,
    const float* __restrict__ b_ih, const float* __restrict__ b_hh)
{
    __shared__ float As[PG_M * PG_PAD];
    __shared__ float Bs[PG_N * PG_PAD];

    int tx = threadIdx.x & 15;   // 16 col groups (4 cols each)
    int ty = threadIdx.x >> 4;   // 16 row groups (8 rows each)
    int mb = (blockIdx.x >> 3) * PG_M;   // 1024 m-tiles
    int nb = (blockIdx.x & 7) * PG_N;    // 8 n-tiles

    int lk = threadIdx.x & 7;    // float4 index within 32-wide K chunk
    int lm = threadIdx.x >> 3;   // 32 rows per load pass

    float acc[8][4];
    #pragma unroll
    for (int i = 0; i < 8; i++)
        #pragma unroll
        for (int j = 0; j < 4; j++) acc[i][j] = 0.f;

    for (int kc = 0; kc < IN_; kc += PG_K) {
        // Load A tile [128 x 32], row-major with pad
        #pragma unroll
        for (int i = 0; i < 4; i++) {
            int m = lm + i * 32;
            float4 v = *(const float4*)(X + (size_t)(mb + m) * IN_ + kc + lk * 4);
            *(float4*)(As + m * PG_PAD + lk * 4) = v;
        }
        // Load B tile [64 x 32] (w_ih0 rows nb..nb+63)
        #pragma unroll
        for (int i = 0; i < 2; i++) {
            int n = lm + i * 32;
            float4 v = *(const float4*)(W + (size_t)(nb + n) * IN_ + kc + lk * 4);
            *(float4*)(Bs + n * PG_PAD + lk * 4) = v;
        }
        __syncthreads();
        #pragma unroll
        for (int k = 0; k < PG_K; k++) {
            float a[8], bv[4];
            #pragma unroll
            for (int i = 0; i < 8; i++) a[i] = As[(ty * 8 + i) * PG_PAD + k];
            #pragma unroll
            for (int j = 0; j < 4; j++) bv[j] = Bs[(tx * 4 + j) * PG_PAD + k];
            #pragma unroll
            for (int i = 0; i < 8; i++)
                #pragma unroll
                for (int j = 0; j < 4; j++)
                    acc[i][j] = fmaf(a[i], bv[j], acc[i][j]);
        }
        __syncthreads();
    }

    // Epilogue: add both biases, store float4
    int n = nb + tx * 4;
    float4 bias = make_float4(b_ih[n] + b_hh[n], b_ih[n + 1] + b_hh[n + 1],
                              b_ih[n + 2] + b_hh[n + 2], b_ih[n + 3] + b_hh[n + 3]);
    #pragma unroll
    for (int i = 0; i < 8; i++) {
        int m = mb + ty * 8 + i;
        float4 v = make_float4(acc[i][0] + bias.x, acc[i][1] + bias.y,
                               acc[i][2] + bias.z, acc[i][3] + bias.w);
        *(float4*)(g_U + (size_t)m * H_ + n) = v;
    }
}

// ---------------- persistent recurrent kernel ----------------
// Grid: 128 CTAs = 8 batch-tiles (16 rows) x 16 col-tiles (32 cols). 256 threads.
// SMEM: wA (w_hh0 slice), wB1 (w_ih1 slice), wB2 (w_hh1 slice), each [512 k][32 n];
//       hs = staged hidden rows [16][512]. Total 229376 B dynamic.
#define RNN_SMEM_BYTES ((3 * 512 * 32 + 16 * 512) * 4)

__device__ __forceinline__ void grid_barrier(unsigned target) {
    __syncthreads();
    if (threadIdx.x == 0) {
        __threadfence();               // release all this CTA's prior stores (device scope)
        atomicAdd(&g_bar, 1u);
        unsigned v;
        do {
            asm volatile("ld.acquire.gpu.u32 %0, [%1];" : "=r"(v) : "l"(&g_bar) : "memory");
        } while (v < target);
    }
    __syncthreads();
}

__device__ __forceinline__ void kloop(const float* __restrict__ Wp,
                                      const float* __restrict__ hs,
                                      int r0, int r1, int lane,
                                      float& acc0, float& acc1) {
    const float4* hv0 = (const float4*)(hs + r0 * 512);
    const float4* hv1 = (const float4*)(hs + r1 * 512);
    #pragma unroll 4
    for (int k4 = 0; k4 < 128; k4++) {
        float4 ha = hv0[k4];
        float4 hb = hv1[k4];
        const float* wp = Wp + k4 * 128 + lane;   // [k][32] layout
        float w0 = wp[0], w1 = wp[32], w2 = wp[64], w3 = wp[96];
        acc0 = fmaf(w0, ha.x, acc0); acc1 = fmaf(w0, hb.x, acc1);
        acc0 = fmaf(w1, ha.y, acc0); acc1 = fmaf(w1, hb.y, acc1);
        acc0 = fmaf(w2, ha.z, acc0); acc1 = fmaf(w2, hb.z, acc1);
        acc0 = fmaf(w3, ha.w, acc0); acc1 = fmaf(w3, hb.w, acc1);
    }
}

__device__ __forceinline__ void stage_h(float* hs, const float* src) {
    // 16 rows x 512 floats contiguous = 2048 float4, 256 threads -> 8 each
    const float4* s4 = (const float4*)src;
    float4* d4 = (float4*)hs;
    #pragma unroll
    for (int i = 0; i < 8; i++) {
        int idx = threadIdx.x + i * 256;
        d4[idx] = __ldcg(s4 + idx);
    }
}

__global__ __launch_bounds__(256, 1) void rnn_kernel(
    const float* __restrict__ w_hh0,
    const float* __restrict__ w_ih1, const float* __restrict__ w_hh1,
    const float* __restrict__ b_ih1, const float* __restrict__ b_hh1)
{
    extern __shared__ float smem[];
    float* wA  = smem;                  // [k][32]
    float* wB1 = smem + 512 * 32;
    float* wB2 = smem + 2 * 512 * 32;
    float* hs  = smem + 3 * 512 * 32;   // [16][512]

    int nn = blockIdx.x & 15, bb = blockIdx.x >> 4;
    int n0 = nn * 32, b0g = bb * 16;
    int w = threadIdx.x >> 5, lane = threadIdx.x & 31;
    int r0 = 2 * w, r1 = 2 * w + 1;

    // Load this CTA's fixed weight slices (once), transposed to [k][n].
    for (int idx = threadIdx.x; idx < 512 * 32; idx += 256) {
        int j = idx & 31, k = idx >> 5;
        wA[idx]  = w_hh0[(n0 + j) * 512 + k];
        wB1[idx] = w_ih1[(n0 + j) * 512 + k];
        wB2[idx] = w_hh1[(n0 + j) * 512 + k];
    }
    float bsum = b_ih1[n0 + lane] + b_hh1[n0 + lane];
    __syncthreads();

    // U prefetch (this thread's 2 outputs per step)
    const float* pU0 = g_U + (size_t)(b0g + r0) * T_ * H_ + n0 + lane;
    const float* pU1 = g_U + (size_t)(b0g + r1) * T_ * H_ + n0 + lane;
    float u0 = __ldcg(pU0), u1 = __ldcg(pU1);

    int outIdx0 = (b0g + r0) * H_ + n0 + lane;
    int outIdx1 = (b0g + r1) * H_ + n0 + lane;

    for (int t = 0; t < T_; t++) {
        int p = t & 1;

        // ---- phase A: h0n = tanh(U_t + h0_old @ w_hh0^T) ----
        __syncthreads();                       // protect hs from prior-iteration readers
        stage_h(hs, g_h0[1 - p] + b0g * H_);
        __syncthreads();

        float acc0 = u0, acc1 = u1;
        if (t + 1 < T_) {                      // prefetch next step's U (hidden behind compute)
            pU0 += H_; pU1 += H_;
            u0 = __ldcg(pU0); u1 = __ldcg(pU1);
        }
        kloop(wA, hs, r0, r1, lane, acc0, acc1);
        __stcg(&g_h0[p][outIdx0], tanhf(acc0));
        __stcg(&g_h0[p][outIdx1], tanhf(acc1));

        grid_barrier((unsigned)(t + 1) * 128u);  // ONE barrier per step

        // ---- phase B: h1n = tanh(h0n @ w_ih1^T + h1_old @ w_hh1^T + b1) ----
        stage_h(hs, g_h0[p] + b0g * H_);       // barrier's syncthreads protects hs
        __syncthreads();
        acc0 = bsum; acc1 = bsum;
        kloop(wB1, hs, r0, r1, lane, acc0, acc1);
        __syncthreads();
        stage_h(hs, g_h1[1 - p] + b0g * H_);
        __syncthreads();
        kloop(wB2, hs, r0, r1, lane, acc0, acc1);
        __stcg(&g_h1[p][outIdx0], tanhf(acc0));
        __stcg(&g_h1[p][outIdx1], tanhf(acc1));
    }
}

// ---------------- fc epilogue: out = h1_final @ fc_w^T + fc_b ----------------
__global__ void fc_kernel(const float* __restrict__ fc_w,
                          const float* __restrict__ fc_b,
                          float* __restrict__ out)
{
    __shared__ float hrow[H_];
    int b = blockIdx.x;
    const float* h1 = g_h1[(T_ - 1) & 1] + b * H_;   // parity of last step = 1
    for (int i = threadIdx.x; i < H_; i += 256) hrow[i] = __ldcg(&h1[i]);
    __syncthreads();

    int o = threadIdx.x;                              // 256 outputs
    float acc = fc_b[o];
    const float4* w4 = (const float4*)(fc_w + (size_t)o * H_);
    #pragma unroll 4
    for (int k4 = 0; k4 < H_ / 4; k4++) {
        float4 wv = __ldg(&w4[k4]);
        acc = fmaf(wv.x, hrow[4 * k4 + 0], acc);
        acc = fmaf(wv.y, hrow[4 * k4 + 1], acc);
        acc = fmaf(wv.z, hrow[4 * k4 + 2], acc);
        acc = fmaf(wv.w, hrow[4 * k4 + 3], acc);
    }
    out[b * OUT_ + o] = acc;
}

// ---------------- launch ----------------
extern "C" void kernel_launch(void* const* d_in, const int* in_sizes, int n_in,
                              void* d_out, int out_size) {
    (void)in_sizes; (void)n_in; (void)out_size;
    const float* x     = (const float*)d_in[0];
    const float* h0in  = (const float*)d_in[1];
    const float* w_ih0 = (const float*)d_in[2];
    const float* w_hh0 = (const float*)d_in[3];
    const float* b_ih0 = (const float*)d_in[4];
    const float* b_hh0 = (const float*)d_in[5];
    const float* w_ih1 = (const float*)d_in[6];
    const float* w_hh1 = (const float*)d_in[7];
    const float* b_ih1 = (const float*)d_in[8];
    const float* b_hh1 = (const float*)d_in[9];
    const float* fc_w  = (const float*)d_in[10];
    const float* fc_b  = (const float*)d_in[11];
    float* out = (float*)d_out;

    init_kernel<<<256, 256>>>(h0in);
    pre_gemm<<<(B_ * T_ / PG_M) * (H_ / PG_N), 256>>>(x, w_ih0, b_ih0, b_hh0);
    cudaFuncSetAttribute(rnn_kernel, cudaFuncAttributeMaxDynamicSharedMemorySize, RNN_SMEM_BYTES);
    rnn_kernel<<<128, 256, RNN_SMEM_BYTES>>>(w_hh0, w_ih1, w_hh1, b_ih1, b_hh1);
    fc_kernel<<<B_, 256>>>(fc_w, fc_b, out);
}

// round 4
// speedup vs baseline: 2.2247x; 2.2247x over previous
#include <cuda_runtime.h>
#include <math.h>

// Problem dims
#define B_   128
#define T_   1024
#define IN_  256
#define H_   512
#define OUT_ 256

typedef unsigned long long u64;

// ---------------- device scratch (no allocations allowed) ----------------
__device__ float g_U[(size_t)B_ * T_ * H_];   // precomputed x@w_ih0^T + b_ih0 + b_hh0, [b*T+t][H]
__device__ float g_h0[2][B_ * H_];            // layer0 hidden, ping-pong by t&1
__device__ float g_h1[2][B_ * H_];            // layer1 hidden, ping-pong by t&1
__device__ unsigned g_bar;                    // grid barrier counter

// ---------------- f32x2 / misc helpers ----------------
__device__ __forceinline__ void fma2(u64& d, u64 a, u64 b) {
    asm("fma.rn.f32x2 %0, %1, %2, %0;" : "+l"(d) : "l"(a), "l"(b));
}
__device__ __forceinline__ float2 unpack2(u64 v) {
    float2 r; asm("mov.b64 {%0, %1}, %2;" : "=f"(r.x), "=f"(r.y) : "l"(v)); return r;
}
__device__ __forceinline__ float tanh_fast(float x) {
    float y; asm("tanh.approx.f32 %0, %1;" : "=f"(y) : "f"(x)); return y;
}

// ---------------- init ----------------
__global__ void init_kernel(const float* __restrict__ h0in) {
    int idx = blockIdx.x * blockDim.x + threadIdx.x;
    if (idx == 0) g_bar = 0u;
    if (idx < B_ * H_) {
        g_h0[1][idx] = h0in[idx];            // read at t=0 (parity 1-p = 1)
        g_h1[1][idx] = h0in[B_ * H_ + idx];
    }
}

// ---------------- precompute GEMM: U = X @ w_ih0^T + (b_ih0 + b_hh0) ----------------
// M = B*T = 131072, N = 512, K = 256. CTA tile 128x64, K-chunks of 32. f32x2 math.
#define PG_M   128
#define PG_N   64
#define PG_K   32
#define PG_PAD 36   // 144B rows, 16B-aligned

__global__ __launch_bounds__(256) void pre_gemm(
    const float* __restrict__ X, const float* __restrict__ W,
    const float* __restrict__ b_ih, const float* __restrict__ b_hh)
{
    __shared__ float As[PG_M * PG_PAD];
    __shared__ float Bs[PG_N * PG_PAD];

    int tx = threadIdx.x & 15;   // 16 col groups
    int ty = threadIdx.x >> 4;   // 16 row groups (8 rows each)
    int mb = (blockIdx.x >> 3) * PG_M;
    int nb = (blockIdx.x & 7) * PG_N;

    int lk = threadIdx.x & 7;
    int lm = threadIdx.x >> 3;

    u64 acc2[8][4];
    #pragma unroll
    for (int i = 0; i < 8; i++)
        #pragma unroll
        for (int j = 0; j < 4; j++) acc2[i][j] = 0ull;

    for (int kc = 0; kc < IN_; kc += PG_K) {
        #pragma unroll
        for (int i = 0; i < 4; i++) {
            int m = lm + i * 32;
            float4 v = *(const float4*)(X + (size_t)(mb + m) * IN_ + kc + lk * 4);
            *(float4*)(As + m * PG_PAD + lk * 4) = v;
        }
        #pragma unroll
        for (int i = 0; i < 2; i++) {
            int n = lm + i * 32;
            float4 v = *(const float4*)(W + (size_t)(nb + n) * IN_ + kc + lk * 4);
            *(float4*)(Bs + n * PG_PAD + lk * 4) = v;
        }
        __syncthreads();
        #pragma unroll
        for (int kq = 0; kq < PG_K / 4; kq++) {
            ulonglong2 a2[8], b2[4];
            #pragma unroll
            for (int i = 0; i < 8; i++)
                a2[i] = *(const ulonglong2*)(As + (ty * 8 + i) * PG_PAD + kq * 4);
            #pragma unroll
            for (int j = 0; j < 4; j++)
                b2[j] = *(const ulonglong2*)(Bs + (tx + 16 * j) * PG_PAD + kq * 4);
            #pragma unroll
            for (int i = 0; i < 8; i++)
                #pragma unroll
                for (int j = 0; j < 4; j++) {
                    fma2(acc2[i][j], a2[i].x, b2[j].x);
                    fma2(acc2[i][j], a2[i].y, b2[j].y);
                }
        }
        __syncthreads();
    }

    // Epilogue: cols are tx + 16j (strided mapping avoids bank conflicts above)
    #pragma unroll
    for (int j = 0; j < 4; j++) {
        int n = nb + tx + 16 * j;
        float bias = b_ih[n] + b_hh[n];
        #pragma unroll
        for (int i = 0; i < 8; i++) {
            int m = mb + ty * 8 + i;
            float2 f = unpack2(acc2[i][j]);
            g_U[(size_t)m * H_ + n] = f.x + f.y + bias;
        }
    }
}

// ---------------- persistent recurrent kernel ----------------
// 128 CTAs = 16 col-tiles (32 cols) x 8 batch-tiles (16 rows). 512 threads = 16 warps.
// Warp w owns k-slice [32w, 32w+32) for ALL 16 rows (weight reads deduplicated once/SM);
// cross-warp reduce via SMEM. Weights in SMEM as quads [q][lane][4k]: one conflict-free
// lane-distinct LDS.128 per warp per 4-k.
#define RNN_THREADS 512
#define NWARP 16
#define RNN_SMEM_BYTES ((3 * 512 * 32 + 16 * 512) * 4)   // 229376 B

__device__ __forceinline__ void grid_barrier(unsigned target) {
    __syncthreads();
    if (threadIdx.x == 0) {
        asm volatile("red.release.gpu.add.u32 [%0], %1;" :: "l"(&g_bar), "r"(1u) : "memory");
        unsigned v;
        do {
            asm volatile("ld.acquire.gpu.u32 %0, [%1];" : "=r"(v) : "l"(&g_bar) : "memory");
        } while (v < target);
    }
    __syncthreads();
}

// hsv: staged hidden as ulonglong2 [16 rows][128]; W4: [128 q][32 lanes] of ulonglong2
__device__ __forceinline__ void kloop(const ulonglong2* __restrict__ W4,
                                      const ulonglong2* __restrict__ hsv,
                                      int w, int lane, u64* __restrict__ acc) {
    #pragma unroll 2
    for (int qq = 0; qq < 8; qq++) {
        int q = w * 8 + qq;
        ulonglong2 wv = W4[q * 32 + lane];           // 4 weights (this lane's col), k..k+3
        const ulonglong2* hq = hsv + q;
        #pragma unroll
        for (int r = 0; r < 16; r++) {
            ulonglong2 h = hq[r * 128];              // broadcast: h[r][4q..4q+3]
            fma2(acc[r], wv.x, h.x);                 // packed (k even, k odd) partials
            fma2(acc[r], wv.y, h.y);
        }
    }
}

__device__ __forceinline__ void stage_h(float4* __restrict__ d4, const float4* __restrict__ s4) {
    #pragma unroll
    for (int i = 0; i < 4; i++) {
        int idx = threadIdx.x + i * RNN_THREADS;
        d4[idx] = __ldcg(s4 + idx);
    }
}

__global__ __launch_bounds__(RNN_THREADS, 1) void rnn_kernel(
    const float* __restrict__ w_hh0,
    const float* __restrict__ w_ih1, const float* __restrict__ w_hh1,
    const float* __restrict__ b_ih1, const float* __restrict__ b_hh1)
{
    extern __shared__ float smem[];
    float* wA  = smem;                   // 512*32 floats, quad layout
    float* wB1 = smem + 512 * 32;
    float* wB2 = smem + 2 * 512 * 32;
    float* hs  = smem + 3 * 512 * 32;    // 16 rows x 512, row-major; reused as reduce buffer
    float* red = hs;

    int nn = blockIdx.x & 15, bb = blockIdx.x >> 4;
    int n0 = nn * 32, b0g = bb * 16;
    int w = threadIdx.x >> 5, lane = threadIdx.x & 31;

    // Load weight slices into quad layout: W4[q*32 + c] = w[n0+c][4q..4q+3]
    for (int idx = threadIdx.x; idx < 128 * 32; idx += RNN_THREADS) {
        int q = idx >> 5, c = idx & 31;
        ((float4*)wA)[idx]  = *(const float4*)(w_hh0 + (size_t)(n0 + c) * H_ + 4 * q);
        ((float4*)wB1)[idx] = *(const float4*)(w_ih1 + (size_t)(n0 + c) * H_ + 4 * q);
        ((float4*)wB2)[idx] = *(const float4*)(w_hh1 + (size_t)(n0 + c) * H_ + 4 * q);
    }
    float bsum = b_ih1[n0 + lane] + b_hh1[n0 + lane];
    __syncthreads();

    // Per-thread output slot: row = warp id, col = lane
    const float* pU = g_U + (size_t)(b0g + w) * T_ * H_ + n0 + lane;
    float u_pre = __ldcg(pU);
    int out0 = (b0g + w) * H_ + n0 + lane;

    const ulonglong2* W4A  = (const ulonglong2*)wA;
    const ulonglong2* W4B1 = (const ulonglong2*)wB1;
    const ulonglong2* W4B2 = (const ulonglong2*)wB2;

    for (int t = 0; t < T_; t++) {
        int p = t & 1;

        // ---- phase A: h0n = tanh(U_t + h0_old @ w_hh0^T) ----
        __syncthreads();                       // prior-iteration red readers done
        stage_h((float4*)hs, (const float4*)(g_h0[1 - p] + b0g * H_));
        __syncthreads();

        u64 acc[16];
        #pragma unroll
        for (int r = 0; r < 16; r++) acc[r] = 0ull;

        float u_cur = u_pre;
        if (t + 1 < T_) { pU += H_; u_pre = __ldcg(pU); }   // prefetch next U

        kloop(W4A, (const ulonglong2*)hs, w, lane, acc);
        __syncthreads();                       // kloop readers of hs done
        #pragma unroll
        for (int r = 0; r < 16; r++) {
            float2 f = unpack2(acc[r]);
            red[(r * NWARP + w) * 32 + lane] = f.x + f.y;
        }
        __syncthreads();
        {
            float s = u_cur;                   // warp w reduces row w
            #pragma unroll
            for (int j = 0; j < NWARP; j++) s += red[(w * NWARP + j) * 32 + lane];
            __stcg(&g_h0[p][out0], tanh_fast(s));
        }

        grid_barrier((unsigned)(t + 1) * 128u);  // ONE barrier per step

        // ---- phase B: h1n = tanh(h0n @ w_ih1^T + h1_old @ w_hh1^T + b1) ----
        stage_h((float4*)hs, (const float4*)(g_h0[p] + b0g * H_));
        __syncthreads();
        #pragma unroll
        for (int r = 0; r < 16; r++) acc[r] = 0ull;
        kloop(W4B1, (const ulonglong2*)hs, w, lane, acc);
        __syncthreads();
        stage_h((float4*)hs, (const float4*)(g_h1[1 - p] + b0g * H_));
        __syncthreads();
        kloop(W4B2, (const ulonglong2*)hs, w, lane, acc);
        __syncthreads();
        #pragma unroll
        for (int r = 0; r < 16; r++) {
            float2 f = unpack2(acc[r]);
            red[(r * NWARP + w) * 32 + lane] = f.x + f.y;
        }
        __syncthreads();
        {
            float s = bsum;
            #pragma unroll
            for (int j = 0; j < NWARP; j++) s += red[(w * NWARP + j) * 32 + lane];
            __stcg(&g_h1[p][out0], tanh_fast(s));
        }
    }
}

// ---------------- fc epilogue: out = h1_final @ fc_w^T + fc_b ----------------
__global__ void fc_kernel(const float* __restrict__ fc_w,
                          const float* __restrict__ fc_b,
                          float* __restrict__ out)
{
    __shared__ float hrow[H_];
    int b = blockIdx.x;
    const float* h1 = g_h1[(T_ - 1) & 1] + b * H_;   // last-step parity = 1
    for (int i = threadIdx.x; i < H_; i += 256) hrow[i] = __ldcg(&h1[i]);
    __syncthreads();

    int o = threadIdx.x;
    float acc = fc_b[o];
    const float4* w4 = (const float4*)(fc_w + (size_t)o * H_);
    #pragma unroll 4
    for (int k4 = 0; k4 < H_ / 4; k4++) {
        float4 wv = __ldg(&w4[k4]);
        acc = fmaf(wv.x, hrow[4 * k4 + 0], acc);
        acc = fmaf(wv.y, hrow[4 * k4 + 1], acc);
        acc = fmaf(wv.z, hrow[4 * k4 + 2], acc);
        acc = fmaf(wv.w, hrow[4 * k4 + 3], acc);
    }
    out[b * OUT_ + o] = acc;
}

// ---------------- launch ----------------
extern "C" void kernel_launch(void* const* d_in, const int* in_sizes, int n_in,
                              void* d_out, int out_size) {
    (void)in_sizes; (void)n_in; (void)out_size;
    const float* x     = (const float*)d_in[0];
    const float* h0in  = (const float*)d_in[1];
    const float* w_ih0 = (const float*)d_in[2];
    const float* w_hh0 = (const float*)d_in[3];
    const float* b_ih0 = (const float*)d_in[4];
    const float* b_hh0 = (const float*)d_in[5];
    const float* w_ih1 = (const float*)d_in[6];
    const float* w_hh1 = (const float*)d_in[7];
    const float* b_ih1 = (const float*)d_in[8];
    const float* b_hh1 = (const float*)d_in[9];
    const float* fc_w  = (const float*)d_in[10];
    const float* fc_b  = (const float*)d_in[11];
    float* out = (float*)d_out;

    init_kernel<<<256, 256>>>(h0in);
    pre_gemm<<<(B_ * T_ / PG_M) * (H_ / PG_N), 256>>>(x, w_ih0, b_ih0, b_hh0);
    cudaFuncSetAttribute(rnn_kernel, cudaFuncAttributeMaxDynamicSharedMemorySize, RNN_SMEM_BYTES);
    rnn_kernel<<<128, RNN_THREADS, RNN_SMEM_BYTES>>>(w_hh0, w_ih1, w_hh1, b_ih1, b_hh1);
    fc_kernel<<<B_, 256>>>(fc_w, fc_b, out);
}

// round 6
// speedup vs baseline: 2.3152x; 1.0407x over previous
#include <cuda_runtime.h>
#include <math.h>

// Problem dims
#define B_   128
#define T_   1024
#define IN_  256
#define H_   512
#define OUT_ 256

typedef unsigned long long u64;

// ---------------- device scratch (no allocations allowed) ----------------
__device__ float g_U[(size_t)B_ * T_ * H_];   // precomputed x@w_ih0^T + b_ih0 + b_hh0, [b*T+t][H]
__device__ float g_h0[2][B_ * H_];            // layer0 hidden, ping-pong by t&1
__device__ float g_h1[2][B_ * H_];            // layer1 hidden, ping-pong by t&1
__device__ unsigned g_bar;                    // grid barrier counter

// ---------------- f32x2 / misc helpers ----------------
__device__ __forceinline__ void fma2(u64& d, u64 a, u64 b) {
    asm("fma.rn.f32x2 %0, %1, %2, %0;" : "+l"(d) : "l"(a), "l"(b));
}
__device__ __forceinline__ float2 unpack2(u64 v) {
    float2 r; asm("mov.b64 {%0, %1}, %2;" : "=f"(r.x), "=f"(r.y) : "l"(v)); return r;
}
__device__ __forceinline__ u64 pack2(float lo, float hi) {
    u64 v; asm("mov.b64 %0, {%1, %2};" : "=l"(v) : "f"(lo), "f"(hi)); return v;
}
__device__ __forceinline__ float tanh_fast(float x) {
    float y; asm("tanh.approx.f32 %0, %1;" : "=f"(y) : "f"(x)); return y;
}

// ---------------- init ----------------
__global__ void init_kernel(const float* __restrict__ h0in) {
    int idx = blockIdx.x * blockDim.x + threadIdx.x;
    if (idx == 0) g_bar = 0u;
    if (idx < B_ * H_) {
        g_h0[1][idx] = h0in[idx];            // initial layer-0 state (boot-staged)
        g_h1[1][idx] = h0in[B_ * H_ + idx];  // initial layer-1 state (read at t=0)
    }
}

// ---------------- precompute GEMM: U = X @ w_ih0^T + (b_ih0 + b_hh0) ----------------
#define PG_M   128
#define PG_N   64
#define PG_K   32
#define PG_PAD 36

__global__ __launch_bounds__(256) void pre_gemm(
    const float* __restrict__ X, const float* __restrict__ W,
    const float* __restrict__ b_ih, const float* __restrict__ b_hh)
{
    __shared__ float As[PG_M * PG_PAD];
    __shared__ float Bs[PG_N * PG_PAD];

    int tx = threadIdx.x & 15;
    int ty = threadIdx.x >> 4;
    int mb = (blockIdx.x >> 3) * PG_M;
    int nb = (blockIdx.x & 7) * PG_N;

    int lk = threadIdx.x & 7;
    int lm = threadIdx.x >> 3;

    u64 acc2[8][4];
    #pragma unroll
    for (int i = 0; i < 8; i++)
        #pragma unroll
        for (int j = 0; j < 4; j++) acc2[i][j] = 0ull;

    for (int kc = 0; kc < IN_; kc += PG_K) {
        #pragma unroll
        for (int i = 0; i < 4; i++) {
            int m = lm + i * 32;
            float4 v = *(const float4*)(X + (size_t)(mb + m) * IN_ + kc + lk * 4);
            *(float4*)(As + m * PG_PAD + lk * 4) = v;
        }
        #pragma unroll
        for (int i = 0; i < 2; i++) {
            int n = lm + i * 32;
            float4 v = *(const float4*)(W + (size_t)(nb + n) * IN_ + kc + lk * 4);
            *(float4*)(Bs + n * PG_PAD + lk * 4) = v;
        }
        __syncthreads();
        #pragma unroll
        for (int kq = 0; kq < PG_K / 4; kq++) {
            ulonglong2 a2[8], b2[4];
            #pragma unroll
            for (int i = 0; i < 8; i++)
                a2[i] = *(const ulonglong2*)(As + (ty * 8 + i) * PG_PAD + kq * 4);
            #pragma unroll
            for (int j = 0; j < 4; j++)
                b2[j] = *(const ulonglong2*)(Bs + (tx + 16 * j) * PG_PAD + kq * 4);
            #pragma unroll
            for (int i = 0; i < 8; i++)
                #pragma unroll
                for (int j = 0; j < 4; j++) {
                    fma2(acc2[i][j], a2[i].x, b2[j].x);
                    fma2(acc2[i][j], a2[i].y, b2[j].y);
                }
        }
        __syncthreads();
    }

    #pragma unroll
    for (int j = 0; j < 4; j++) {
        int n = nb + tx + 16 * j;
        float bias = b_ih[n] + b_hh[n];
        #pragma unroll
        for (int i = 0; i < 8; i++) {
            int m = mb + ty * 8 + i;
            float2 f = unpack2(acc2[i][j]);
            g_U[(size_t)m * H_ + n] = f.x + f.y + bias;
        }
    }
}

// ---------------- persistent recurrent kernel ----------------
// 128 CTAs = 16 col-tiles (32 cols) x 8 batch-tiles (16 rows). 512 threads = 16 warps.
// Warp w owns k-slice [32w, 32w+32). w_hh0 lives in REGISTERS (32/thread).
// SMEM: wB1, wB2 (quad layout, 64KB each) + hs0 + hs1 (32KB each) + red (32KB) = 224KB.
// Schedule per step: A(reads hs0) -> barrier -> stage hs0,hs1 -> B. Phase A never
// touches global h: hs0 (staged for B at step t-1) IS h0[t-1].
#define RNN_THREADS 512
#define NWARP 16
#define RNN_SMEM_BYTES ((2 * 512 * 32 + 3 * 16 * 512) * 4)   // 229376 B

__device__ __forceinline__ void grid_barrier(unsigned target) {
    __syncthreads();
    if (threadIdx.x == 0) {
        asm volatile("red.release.gpu.add.u32 [%0], %1;" :: "l"(&g_bar), "r"(1u) : "memory");
        unsigned v;
        do {
            asm volatile("ld.acquire.gpu.u32 %0, [%1];" : "=r"(v) : "l"(&g_bar) : "memory");
        } while (v < target);
    }
    __syncthreads();
}

// SMEM-weight kloop: W4 quad layout [q][lane]; hsv [16 rows][128 quads]
__device__ __forceinline__ void kloop_smem(const ulonglong2* __restrict__ W4,
                                           const ulonglong2* __restrict__ hsv,
                                           int w, int lane, u64* __restrict__ acc) {
    #pragma unroll 2
    for (int qq = 0; qq < 8; qq++) {
        int q = w * 8 + qq;
        ulonglong2 wv = W4[q * 32 + lane];
        const ulonglong2* hq = hsv + q;
        #pragma unroll
        for (int r = 0; r < 16; r++) {
            ulonglong2 h = hq[r * 128];
            fma2(acc[r], wv.x, h.x);
            fma2(acc[r], wv.y, h.y);
        }
    }
}

// Register-weight kloop (phase A): weights preloaded in wreg[16] (u64 pairs)
__device__ __forceinline__ void kloop_reg(const u64* __restrict__ wreg,
                                          const ulonglong2* __restrict__ hsv,
                                          int w, u64* __restrict__ acc) {
    #pragma unroll 2
    for (int qq = 0; qq < 8; qq++) {
        int q = w * 8 + qq;
        u64 w0 = wreg[2 * qq], w1 = wreg[2 * qq + 1];
        const ulonglong2* hq = hsv + q;
        #pragma unroll
        for (int r = 0; r < 16; r++) {
            ulonglong2 h = hq[r * 128];
            fma2(acc[r], w0, h.x);
            fma2(acc[r], w1, h.y);
        }
    }
}

__device__ __forceinline__ void stage1(float4* __restrict__ d, const float4* __restrict__ s) {
    #pragma unroll
    for (int i = 0; i < 4; i++) {
        int idx = threadIdx.x + i * RNN_THREADS;
        d[idx] = __ldcg(s + idx);
    }
}

__device__ __forceinline__ void stage2(float4* __restrict__ d0, const float4* __restrict__ s0,
                                       float4* __restrict__ d1, const float4* __restrict__ s1_) {
    float4 v0[4], v1[4];
    #pragma unroll
    for (int i = 0; i < 4; i++) v0[i] = __ldcg(s0 + threadIdx.x + i * RNN_THREADS);
    #pragma unroll
    for (int i = 0; i < 4; i++) v1[i] = __ldcg(s1_ + threadIdx.x + i * RNN_THREADS);
    #pragma unroll
    for (int i = 0; i < 4; i++) d0[threadIdx.x + i * RNN_THREADS] = v0[i];
    #pragma unroll
    for (int i = 0; i < 4; i++) d1[threadIdx.x + i * RNN_THREADS] = v1[i];
}

__global__ __launch_bounds__(RNN_THREADS, 1) void rnn_kernel(
    const float* __restrict__ w_hh0,
    const float* __restrict__ w_ih1, const float* __restrict__ w_hh1,
    const float* __restrict__ b_ih1, const float* __restrict__ b_hh1)
{
    extern __shared__ float smem[];
    float* wB1 = smem;                    // 512*32 floats, quad layout
    float* wB2 = smem + 512 * 32;
    float* hs0 = smem + 2 * 512 * 32;     // 16 x 512
    float* hs1 = hs0 + 16 * 512;
    float* red = hs1 + 16 * 512;          // 16 x 16 x 32

    int nn = blockIdx.x & 15, bb = blockIdx.x >> 4;
    int n0 = nn * 32, b0g = bb * 16;
    int w = threadIdx.x >> 5, lane = threadIdx.x & 31;

    // SMEM weights (phase B): quad layout W4[q*32 + c] = w[n0+c][4q..4q+3]
    for (int idx = threadIdx.x; idx < 128 * 32; idx += RNN_THREADS) {
        int q = idx >> 5, c = idx & 31;
        ((float4*)wB1)[idx] = *(const float4*)(w_ih1 + (size_t)(n0 + c) * H_ + 4 * q);
        ((float4*)wB2)[idx] = *(const float4*)(w_hh1 + (size_t)(n0 + c) * H_ + 4 * q);
    }
    // Register weights (phase A): this thread's col = n0+lane, k-slice [32w, 32w+32)
    u64 wreg[16];
    {
        const float4* wp = (const float4*)(w_hh0 + (size_t)(n0 + lane) * H_ + 32 * w);
        #pragma unroll
        for (int i = 0; i < 8; i++) {
            float4 v = __ldg(wp + i);
            wreg[2 * i]     = pack2(v.x, v.y);
            wreg[2 * i + 1] = pack2(v.z, v.w);
        }
    }
    float bsum = b_ih1[n0 + lane] + b_hh1[n0 + lane];

    // Boot: hs0 <- initial layer-0 hidden state
    __syncthreads();
    stage1((float4*)hs0, (const float4*)(g_h0[1] + b0g * H_));
    __syncthreads();

    const float* pU = g_U + (size_t)(b0g + w) * T_ * H_ + n0 + lane;
    float u_pre = __ldcg(pU);
    int out0 = (b0g + w) * H_ + n0 + lane;

    const ulonglong2* hs0v = (const ulonglong2*)hs0;
    const ulonglong2* hs1v = (const ulonglong2*)hs1;
    const ulonglong2* W4B1 = (const ulonglong2*)wB1;
    const ulonglong2* W4B2 = (const ulonglong2*)wB2;

    for (int t = 0; t < T_; t++) {
        int p = t & 1;

        // ---- phase A: h0[t] = tanh(U[t] + hs0 @ w_hh0^T)  (hs0 holds h0[t-1]) ----
        u64 acc[16];
        #pragma unroll
        for (int r = 0; r < 16; r++) acc[r] = 0ull;

        float u_cur = u_pre;
        if (t + 1 < T_) { pU += H_; u_pre = __ldcg(pU); }   // prefetch next U

        kloop_reg(wreg, hs0v, w, acc);
        __syncthreads();                       // s1: prev-iter red readers done
        #pragma unroll
        for (int r = 0; r < 16; r++) {
            float2 f = unpack2(acc[r]);
            red[(r * NWARP + w) * 32 + lane] = f.x + f.y;
        }
        __syncthreads();                       // s2: red visible
        {
            float s = u_cur;                   // warp w reduces row w
            #pragma unroll
            for (int j = 0; j < NWARP; j++) s += red[(w * NWARP + j) * 32 + lane];
            __stcg(&g_h0[p][out0], tanh_fast(s));
        }

        grid_barrier((unsigned)(t + 1) * 128u);  // ONE barrier per step

        // ---- stage both B operands with one exposed latency ----
        stage2((float4*)hs0, (const float4*)(g_h0[p] + b0g * H_),
               (float4*)hs1, (const float4*)(g_h1[1 - p] + b0g * H_));
        __syncthreads();                       // s3: hs0/hs1 visible

        // ---- phase B: h1[t] = tanh(hs0 @ w_ih1^T + hs1 @ w_hh1^T + b1) ----
        #pragma unroll
        for (int r = 0; r < 16; r++) acc[r] = 0ull;
        kloop_smem(W4B1, hs0v, w, lane, acc);
        kloop_smem(W4B2, hs1v, w, lane, acc);
        #pragma unroll
        for (int r = 0; r < 16; r++) {          // red WAR vs A-read covered by barrier
            float2 f = unpack2(acc[r]);
            red[(r * NWARP + w) * 32 + lane] = f.x + f.y;
        }
        __syncthreads();                       // s4: red visible
        {
            float s = bsum;
            #pragma unroll
            for (int j = 0; j < NWARP; j++) s += red[(w * NWARP + j) * 32 + lane];
            __stcg(&g_h1[p][out0], tanh_fast(s));
        }
        // hs0 retained: it IS h0[t], consumed by phase A of step t+1.
    }
}

// ---------------- fc epilogue: out = h1_final @ fc_w^T + fc_b ----------------
__global__ void fc_kernel(const float* __restrict__ fc_w,
                          const float* __restrict__ fc_b,
                          float* __restrict__ out)
{
    __shared__ float hrow[H_];
    int b = blockIdx.x;
    const float* h1 = g_h1[(T_ - 1) & 1] + b * H_;   // last-step parity = 1
    for (int i = threadIdx.x; i < H_; i += 256) hrow[i] = __ldcg(&h1[i]);
    __syncthreads();

    int o = threadIdx.x;
    float acc = fc_b[o];
    const float4* w4 = (const float4*)(fc_w + (size_t)o * H_);
    #pragma unroll 4
    for (int k4 = 0; k4 < H_ / 4; k4++) {
        float4 wv = __ldg(&w4[k4]);
        acc = fmaf(wv.x, hrow[4 * k4 + 0], acc);
        acc = fmaf(wv.y, hrow[4 * k4 + 1], acc);
        acc = fmaf(wv.z, hrow[4 * k4 + 2], acc);
        acc = fmaf(wv.w, hrow[4 * k4 + 3], acc);
    }
    out[b * OUT_ + o] = acc;
}

// ---------------- launch ----------------
extern "C" void kernel_launch(void* const* d_in, const int* in_sizes, int n_in,
                              void* d_out, int out_size) {
    (void)in_sizes; (void)n_in; (void)out_size;
    const float* x     = (const float*)d_in[0];
    const float* h0in  = (const float*)d_in[1];
    const float* w_ih0 = (const float*)d_in[2];
    const float* w_hh0 = (const float*)d_in[3];
    const float* b_ih0 = (const float*)d_in[4];
    const float* b_hh0 = (const float*)d_in[5];
    const float* w_ih1 = (const float*)d_in[6];
    const float* w_hh1 = (const float*)d_in[7];
    const float* b_ih1 = (const float*)d_in[8];
    const float* b_hh1 = (const float*)d_in[9];
    const float* fc_w  = (const float*)d_in[10];
    const float* fc_b  = (const float*)d_in[11];
    float* out = (float*)d_out;

    init_kernel<<<256, 256>>>(h0in);
    pre_gemm<<<(B_ * T_ / PG_M) * (H_ / PG_N), 256>>>(x, w_ih0, b_ih0, b_hh0);
    cudaFuncSetAttribute(rnn_kernel, cudaFuncAttributeMaxDynamicSharedMemorySize, RNN_SMEM_BYTES);
    rnn_kernel<<<128, RNN_THREADS, RNN_SMEM_BYTES>>>(w_hh0, w_ih1, w_hh1, b_ih1, b_hh1);
    fc_kernel<<<B_, 256>>>(fc_w, fc_b, out);
}